// round 15
// baseline (speedup 1.0000x reference)
#include <cuda_runtime.h>
#include <math_constants.h>

#define B_  512
#define S_  256
#define D_  64
#define H_  64
#define E_  8
#define HE_ 512   // H_*E_

// Scratch: [B,H] set-representation (k1 -> k2a), [B,32] fc1 output (k2a -> k2b).
__device__ float g_t[B_ * H_];
__device__ float g_y[B_ * 32];

// ---------------------------------------------------------------------------
// Packed fp32x2 helpers (sm_103a FFMA2 — only reachable via PTX)
// ---------------------------------------------------------------------------
__device__ __forceinline__ void ffma2(unsigned long long& acc,
                                      unsigned long long a,
                                      unsigned long long b) {
    asm("fma.rn.f32x2 %0, %1, %2, %0;" : "+l"(acc) : "l"(a), "l"(b));
}
__device__ __forceinline__ unsigned long long pack2(float x, float y) {
    unsigned long long r;
    asm("mov.b64 %0, {%1, %2};" : "=l"(r) : "f"(x), "f"(y));
    return r;
}
__device__ __forceinline__ void unpack2(unsigned long long v, float& x, float& y) {
    asm("mov.b64 {%0, %1}, %2;" : "=f"(x), "=f"(y) : "l"(v));
}

// ---------------------------------------------------------------------------
// Kernel 1: fused  leaky(X @ Wc) -> view[B,S,E,H] -> max over E -> sum over S
// One block per batch b. 256 threads = 256 s-rows. Wc in 128 KB SMEM.
// Inner loop uses packed FFMA2: 2 columns per instruction.
// ---------------------------------------------------------------------------
__global__ void __launch_bounds__(256, 1)
k1_gemm_maxsum(const float* __restrict__ X, const float* __restrict__ Wc)
{
    extern __shared__ float sWc[];          // 32768 floats = 128 KB
    __shared__ float sSum[H_];

    const int b    = blockIdx.x;
    const int tid  = threadIdx.x;
    const int lane = tid & 31;

    // Stage Wc (coalesced float4).
    {
        const float4* src = reinterpret_cast<const float4*>(Wc);
        float4* dst = reinterpret_cast<float4*>(sWc);
        #pragma unroll
        for (int i = tid; i < (D_ * HE_) / 4; i += 256)
            dst[i] = src[i];
    }
    if (tid < H_) sSum[tid] = 0.0f;
    __syncthreads();

    // X row (64 floats) in registers.
    float x[D_];
    {
        const float4* xr = reinterpret_cast<const float4*>(
            X + ((size_t)b * S_ + tid) * D_);
        #pragma unroll
        for (int i = 0; i < D_ / 4; ++i) {
            float4 v = xr[i];
            x[4*i+0] = v.x; x[4*i+1] = v.y; x[4*i+2] = v.z; x[4*i+3] = v.w;
        }
    }

    // SMEM viewed as packed f32x2 pairs: 4 floats = ulonglong2 (two f32x2).
    const ulonglong2* sWc2 = reinterpret_cast<const ulonglong2*>(sWc);

    #pragma unroll 1
    for (int ht = 0; ht < 4; ++ht) {        // 4 tiles x 16 columns
        const int h0 = ht * 16;
        float m[16];
        #pragma unroll
        for (int i = 0; i < 16; ++i) m[i] = -CUDART_INF_F;

        #pragma unroll 1
        for (int e = 0; e < E_; ++e) {
            unsigned long long acc[8];
            #pragma unroll
            for (int i = 0; i < 8; ++i) acc[i] = 0ull;   // {0.f, 0.f}

            const int cbase = (e * H_ + h0) >> 2;         // ulonglong2 index
            #pragma unroll
            for (int k = 0; k < D_; ++k) {
                const unsigned long long xx = pack2(x[k], x[k]);
                const ulonglong2* row = sWc2 + k * (HE_ / 4) + cbase;
                ulonglong2 w0 = row[0];
                ulonglong2 w1 = row[1];
                ulonglong2 w2 = row[2];
                ulonglong2 w3 = row[3];
                ffma2(acc[0], xx, w0.x);  ffma2(acc[1], xx, w0.y);
                ffma2(acc[2], xx, w1.x);  ffma2(acc[3], xx, w1.y);
                ffma2(acc[4], xx, w2.x);  ffma2(acc[5], xx, w2.y);
                ffma2(acc[6], xx, w3.x);  ffma2(acc[7], xx, w3.y);
            }
            #pragma unroll
            for (int i = 0; i < 8; ++i) {
                float a, c;
                unpack2(acc[i], a, c);
                m[2*i + 0] = fmaxf(m[2*i + 0], a);
                m[2*i + 1] = fmaxf(m[2*i + 1], c);
            }
        }

        // LeakyReLU is monotonic: apply once after max over E.
        #pragma unroll
        for (int i = 0; i < 16; ++i) {
            float v = m[i];
            v = v >= 0.f ? v : 0.01f * v;
            #pragma unroll
            for (int off = 16; off > 0; off >>= 1)
                v += __shfl_down_sync(0xffffffffu, v, off);
            if (lane == 0) atomicAdd(&sSum[h0 + i], v);
        }
    }
    __syncthreads();
    if (tid < H_) g_t[b * H_ + tid] = sSum[tid];
}

// ---------------------------------------------------------------------------
// Kernel 2a: fc1  y[b,j] = g_t[b,:] . fc1_w[j,:] + fc1_b[j]
// 32 blocks x 512 threads; block handles 16 rows x 32 features.
// fc1_w transposed in SMEM so lanes (j) read consecutive floats.
// ---------------------------------------------------------------------------
__global__ void __launch_bounds__(512, 1)
k2a_fc1(const float* __restrict__ fc1_w, const float* __restrict__ fc1_b)
{
    __shared__ float sW1t[64 * 32];         // [k][j], 8 KB
    __shared__ float sT[16 * 64];           // 16 rows of g_t, 4 KB

    const int tid = threadIdx.x;
    const int r   = tid >> 5;               // 0..15 local row
    const int j   = tid & 31;               // feature

    // Transposed load of fc1_w [32,64] -> sW1t[k*32+j].
    for (int i = tid; i < 32 * 64; i += 512) {
        int jj = i >> 6, kk = i & 63;
        sW1t[kk * 32 + jj] = fc1_w[i];
    }
    // Rows of g_t for this block.
    {
        const int row0 = blockIdx.x * 16;
        const float4* src = reinterpret_cast<const float4*>(&g_t[row0 * 64]);
        float4* dst = reinterpret_cast<float4*>(sT);
        for (int i = tid; i < (16 * 64) / 4; i += 512) dst[i] = src[i];
    }
    __syncthreads();

    float a = __ldg(&fc1_b[j]);
    #pragma unroll
    for (int k = 0; k < 64; ++k)
        a = fmaf(sT[r * 64 + k], sW1t[k * 32 + j], a);

    g_y[(blockIdx.x * 16 + r) * 32 + j] = a;
}

// ---------------------------------------------------------------------------
// Kernel 2b: BatchNorm1d (training stats, two-pass) -> leaky -> fc2
// Single block of 512 threads; one batch row per thread.
// ---------------------------------------------------------------------------
__global__ void __launch_bounds__(512, 1)
k2b_bn_fc2(const float* __restrict__ gamma, const float* __restrict__ beta,
           const float* __restrict__ fc2_w, const float* __restrict__ fc2_b,
           float* __restrict__ out)
{
    __shared__ float sPart[32 * 16];
    __shared__ float sMu[32];
    __shared__ float sRstd[32];

    const int tid  = threadIdx.x;
    const int lane = tid & 31;
    const int warp = tid >> 5;

    float y[32];
    {
        const float4* yr = reinterpret_cast<const float4*>(&g_y[tid * 32]);
        #pragma unroll
        for (int i = 0; i < 8; ++i) {
            float4 v = yr[i];
            y[4*i+0] = v.x; y[4*i+1] = v.y; y[4*i+2] = v.z; y[4*i+3] = v.w;
        }
    }

    // Pass 1: mean
    #pragma unroll
    for (int j = 0; j < 32; ++j) {
        float s = y[j];
        #pragma unroll
        for (int off = 16; off > 0; off >>= 1)
            s += __shfl_down_sync(0xffffffffu, s, off);
        if (lane == 0) sPart[j * 16 + warp] = s;
    }
    __syncthreads();
    if (tid < 32) {
        float s = 0.f;
        #pragma unroll
        for (int w = 0; w < 16; ++w) s += sPart[tid * 16 + w];
        sMu[tid] = s * (1.0f / 512.0f);
    }
    __syncthreads();

    // Pass 2: biased variance
    #pragma unroll
    for (int j = 0; j < 32; ++j) {
        float d = y[j] - sMu[j];
        float s = d * d;
        #pragma unroll
        for (int off = 16; off > 0; off >>= 1)
            s += __shfl_down_sync(0xffffffffu, s, off);
        if (lane == 0) sPart[j * 16 + warp] = s;
    }
    __syncthreads();
    if (tid < 32) {
        float s = 0.f;
        #pragma unroll
        for (int w = 0; w < 16; ++w) s += sPart[tid * 16 + w];
        sRstd[tid] = rsqrtf(s * (1.0f / 512.0f) + 1e-5f);
    }
    __syncthreads();

    float acc = __ldg(&fc2_b[0]);
    #pragma unroll
    for (int j = 0; j < 32; ++j) {
        float v = (y[j] - sMu[j]) * sRstd[j] * __ldg(&gamma[j]) + __ldg(&beta[j]);
        v = v >= 0.f ? v : 0.01f * v;
        acc = fmaf(v, __ldg(&fc2_w[j]), acc);
    }
    out[tid] = acc;
}

// ---------------------------------------------------------------------------
extern "C" void kernel_launch(void* const* d_in, const int* in_sizes, int n_in,
                              void* d_out, int out_size)
{
    const float* X     = (const float*)d_in[0];
    const float* Wc    = (const float*)d_in[1];
    const float* fc1_w = (const float*)d_in[2];
    const float* fc1_b = (const float*)d_in[3];
    const float* gamma = (const float*)d_in[4];
    const float* beta  = (const float*)d_in[5];
    const float* fc2_w = (const float*)d_in[6];
    const float* fc2_b = (const float*)d_in[7];
    float* out = (float*)d_out;

    const int smem_k1 = D_ * HE_ * sizeof(float);   // 128 KB
    cudaFuncSetAttribute(k1_gemm_maxsum,
                         cudaFuncAttributeMaxDynamicSharedMemorySize, smem_k1);

    k1_gemm_maxsum<<<B_, 256, smem_k1>>>(X, Wc);
    k2a_fc1<<<32, 512>>>(fc1_w, fc1_b);
    k2b_bn_fc2<<<1, 512>>>(gamma, beta, fc2_w, fc2_b, out);
}

// round 16
// speedup vs baseline: 1.0572x; 1.0572x over previous
#include <cuda_runtime.h>
#include <math_constants.h>

#define B_  512
#define S_  256
#define D_  64
#define H_  64
#define E_  8
#define HE_ 512   // H_*E_

// Scratch: [B,H] set-representation (k1 -> k2a), [B,32] fc1 output (k2a -> k2b).
__device__ float g_t[B_ * H_];
__device__ float g_y[B_ * 32];

// ---------------------------------------------------------------------------
// Packed fp32x2 helpers (sm_103a FFMA2 — only reachable via PTX)
// ---------------------------------------------------------------------------
__device__ __forceinline__ void ffma2(unsigned long long& acc,
                                      unsigned long long a,
                                      unsigned long long b) {
    asm("fma.rn.f32x2 %0, %1, %2, %0;" : "+l"(acc) : "l"(a), "l"(b));
}
__device__ __forceinline__ unsigned long long pack2(float x, float y) {
    unsigned long long r;
    asm("mov.b64 %0, {%1, %2};" : "=l"(r) : "f"(x), "f"(y));
    return r;
}
__device__ __forceinline__ void unpack2(unsigned long long v, float& x, float& y) {
    asm("mov.b64 {%0, %1}, %2;" : "=f"(x), "=f"(y) : "l"(v));
}

// ---------------------------------------------------------------------------
// Kernel 1: fused  leaky(X @ Wc) -> view[B,S,E,H] -> max over E -> sum over S
// One block per batch b. 256 threads = 256 s-rows. Wc in 128 KB SMEM.
// Inner loop uses packed FFMA2: 2 columns per instruction.
// ---------------------------------------------------------------------------
__global__ void __launch_bounds__(256, 1)
k1_gemm_maxsum(const float* __restrict__ X, const float* __restrict__ Wc)
{
    extern __shared__ float sWc[];          // 32768 floats = 128 KB
    __shared__ float sSum[H_];

    const int b    = blockIdx.x;
    const int tid  = threadIdx.x;
    const int lane = tid & 31;

    // Stage Wc (coalesced float4).
    {
        const float4* src = reinterpret_cast<const float4*>(Wc);
        float4* dst = reinterpret_cast<float4*>(sWc);
        #pragma unroll
        for (int i = tid; i < (D_ * HE_) / 4; i += 256)
            dst[i] = src[i];
    }
    if (tid < H_) sSum[tid] = 0.0f;
    __syncthreads();

    // X row (64 floats) in registers.
    float x[D_];
    {
        const float4* xr = reinterpret_cast<const float4*>(
            X + ((size_t)b * S_ + tid) * D_);
        #pragma unroll
        for (int i = 0; i < D_ / 4; ++i) {
            float4 v = xr[i];
            x[4*i+0] = v.x; x[4*i+1] = v.y; x[4*i+2] = v.z; x[4*i+3] = v.w;
        }
    }

    // SMEM viewed as packed f32x2 pairs: 4 floats = ulonglong2 (two f32x2).
    const ulonglong2* sWc2 = reinterpret_cast<const ulonglong2*>(sWc);

    #pragma unroll 1
    for (int ht = 0; ht < 4; ++ht) {        // 4 tiles x 16 columns
        const int h0 = ht * 16;
        float m[16];
        #pragma unroll
        for (int i = 0; i < 16; ++i) m[i] = -CUDART_INF_F;

        #pragma unroll 1
        for (int e = 0; e < E_; ++e) {
            unsigned long long acc[8];
            #pragma unroll
            for (int i = 0; i < 8; ++i) acc[i] = 0ull;   // {0.f, 0.f}

            const int cbase = (e * H_ + h0) >> 2;         // ulonglong2 index
            #pragma unroll
            for (int k = 0; k < D_; ++k) {
                const unsigned long long xx = pack2(x[k], x[k]);
                const ulonglong2* row = sWc2 + k * (HE_ / 4) + cbase;
                ulonglong2 w0 = row[0];
                ulonglong2 w1 = row[1];
                ulonglong2 w2 = row[2];
                ulonglong2 w3 = row[3];
                ffma2(acc[0], xx, w0.x);  ffma2(acc[1], xx, w0.y);
                ffma2(acc[2], xx, w1.x);  ffma2(acc[3], xx, w1.y);
                ffma2(acc[4], xx, w2.x);  ffma2(acc[5], xx, w2.y);
                ffma2(acc[6], xx, w3.x);  ffma2(acc[7], xx, w3.y);
            }
            #pragma unroll
            for (int i = 0; i < 8; ++i) {
                float a, c;
                unpack2(acc[i], a, c);
                m[2*i + 0] = fmaxf(m[2*i + 0], a);
                m[2*i + 1] = fmaxf(m[2*i + 1], c);
            }
        }

        // LeakyReLU is monotonic: apply once after max over E.
        #pragma unroll
        for (int i = 0; i < 16; ++i) {
            float v = m[i];
            v = v >= 0.f ? v : 0.01f * v;
            #pragma unroll
            for (int off = 16; off > 0; off >>= 1)
                v += __shfl_down_sync(0xffffffffu, v, off);
            if (lane == 0) atomicAdd(&sSum[h0 + i], v);
        }
    }
    __syncthreads();
    if (tid < H_) g_t[b * H_ + tid] = sSum[tid];
}

// ---------------------------------------------------------------------------
// Kernel 2a: fc1  y[b,j] = g_t[b,:] . fc1_w[j,:] + fc1_b[j]
// 32 blocks x 512 threads; block handles 16 rows x 32 features.
// fc1_w transposed in SMEM so lanes (j) read consecutive floats.
// ---------------------------------------------------------------------------
__global__ void __launch_bounds__(512, 1)
k2a_fc1(const float* __restrict__ fc1_w, const float* __restrict__ fc1_b)
{
    __shared__ float sW1t[64 * 32];         // [k][j], 8 KB
    __shared__ float sT[16 * 64];           // 16 rows of g_t, 4 KB

    const int tid = threadIdx.x;
    const int r   = tid >> 5;               // 0..15 local row
    const int j   = tid & 31;               // feature

    // Transposed load of fc1_w [32,64] -> sW1t[k*32+j].
    for (int i = tid; i < 32 * 64; i += 512) {
        int jj = i >> 6, kk = i & 63;
        sW1t[kk * 32 + jj] = fc1_w[i];
    }
    // Rows of g_t for this block.
    {
        const int row0 = blockIdx.x * 16;
        const float4* src = reinterpret_cast<const float4*>(&g_t[row0 * 64]);
        float4* dst = reinterpret_cast<float4*>(sT);
        for (int i = tid; i < (16 * 64) / 4; i += 512) dst[i] = src[i];
    }
    __syncthreads();

    float a = __ldg(&fc1_b[j]);
    #pragma unroll
    for (int k = 0; k < 64; ++k)
        a = fmaf(sT[r * 64 + k], sW1t[k * 32 + j], a);

    g_y[(blockIdx.x * 16 + r) * 32 + j] = a;
}

// ---------------------------------------------------------------------------
// Kernel 2b: BatchNorm1d (training stats, two-pass) -> leaky -> fc2
// Single block of 512 threads; one batch row per thread.
// ---------------------------------------------------------------------------
__global__ void __launch_bounds__(512, 1)
k2b_bn_fc2(const float* __restrict__ gamma, const float* __restrict__ beta,
           const float* __restrict__ fc2_w, const float* __restrict__ fc2_b,
           float* __restrict__ out)
{
    __shared__ float sPart[32 * 16];
    __shared__ float sMu[32];
    __shared__ float sRstd[32];

    const int tid  = threadIdx.x;
    const int lane = tid & 31;
    const int warp = tid >> 5;

    float y[32];
    {
        const float4* yr = reinterpret_cast<const float4*>(&g_y[tid * 32]);
        #pragma unroll
        for (int i = 0; i < 8; ++i) {
            float4 v = yr[i];
            y[4*i+0] = v.x; y[4*i+1] = v.y; y[4*i+2] = v.z; y[4*i+3] = v.w;
        }
    }

    // Pass 1: mean
    #pragma unroll
    for (int j = 0; j < 32; ++j) {
        float s = y[j];
        #pragma unroll
        for (int off = 16; off > 0; off >>= 1)
            s += __shfl_down_sync(0xffffffffu, s, off);
        if (lane == 0) sPart[j * 16 + warp] = s;
    }
    __syncthreads();
    if (tid < 32) {
        float s = 0.f;
        #pragma unroll
        for (int w = 0; w < 16; ++w) s += sPart[tid * 16 + w];
        sMu[tid] = s * (1.0f / 512.0f);
    }
    __syncthreads();

    // Pass 2: biased variance
    #pragma unroll
    for (int j = 0; j < 32; ++j) {
        float d = y[j] - sMu[j];
        float s = d * d;
        #pragma unroll
        for (int off = 16; off > 0; off >>= 1)
            s += __shfl_down_sync(0xffffffffu, s, off);
        if (lane == 0) sPart[j * 16 + warp] = s;
    }
    __syncthreads();
    if (tid < 32) {
        float s = 0.f;
        #pragma unroll
        for (int w = 0; w < 16; ++w) s += sPart[tid * 16 + w];
        sRstd[tid] = rsqrtf(s * (1.0f / 512.0f) + 1e-5f);
    }
    __syncthreads();

    float acc = __ldg(&fc2_b[0]);
    #pragma unroll
    for (int j = 0; j < 32; ++j) {
        float v = (y[j] - sMu[j]) * sRstd[j] * __ldg(&gamma[j]) + __ldg(&beta[j]);
        v = v >= 0.f ? v : 0.01f * v;
        acc = fmaf(v, __ldg(&fc2_w[j]), acc);
    }
    out[tid] = acc;
}

// ---------------------------------------------------------------------------
extern "C" void kernel_launch(void* const* d_in, const int* in_sizes, int n_in,
                              void* d_out, int out_size)
{
    const float* X     = (const float*)d_in[0];
    const float* Wc    = (const float*)d_in[1];
    const float* fc1_w = (const float*)d_in[2];
    const float* fc1_b = (const float*)d_in[3];
    const float* gamma = (const float*)d_in[4];
    const float* beta  = (const float*)d_in[5];
    const float* fc2_w = (const float*)d_in[6];
    const float* fc2_b = (const float*)d_in[7];
    float* out = (float*)d_out;

    const int smem_k1 = D_ * HE_ * sizeof(float);   // 128 KB
    cudaFuncSetAttribute(k1_gemm_maxsum,
                         cudaFuncAttributeMaxDynamicSharedMemorySize, smem_k1);

    k1_gemm_maxsum<<<B_, 256, smem_k1>>>(X, Wc);
    k2a_fc1<<<32, 512>>>(fc1_w, fc1_b);
    k2b_bn_fc2<<<1, 512>>>(gamma, beta, fc2_w, fc2_b, out);
}